// round 15
// baseline (speedup 1.0000x reference)
#include <cuda_runtime.h>
#include <cuda_bf16.h>
#include <cstdint>

// Shapes fixed by the problem.
#define M_DIM 4096
#define N_DIM 4096
#define K_DIM 4096

// ---------------- scratch (static __device__; no runtime alloc) ----------------
__device__ __align__(256) __nv_bfloat16 g_qx[(size_t)M_DIM * K_DIM];  // quantized activations (ints in bf16)
__device__ __align__(256) __nv_bfloat16 g_qw[(size_t)N_DIM * K_DIM];  // quantized weights (ints in bf16)
__device__ float g_st[M_DIM];
__device__ float g_so[N_DIM];

// ---------------- fused prep kernel (unchanged) ----------------
__global__ __launch_bounds__(256) void prep_kernel(const float* __restrict__ w,
                                                   const float* __restrict__ x) {
    __shared__ float s[64 * 65];
    __shared__ float red[8];
    const int tid = threadIdx.x;

    if (blockIdx.x < N_DIM) {
        // ======== weight quant path ========
        const int o = blockIdx.x;
        const float4* wr = (const float4*)(w + (size_t)o * K_DIM);

        float4 v[4];
        float m = 0.f;
        #pragma unroll
        for (int p = 0; p < 4; p++) {
            v[p] = wr[tid + p * 256];
            m = fmaxf(m, fmaxf(fmaxf(fabsf(v[p].x), fabsf(v[p].y)),
                               fmaxf(fabsf(v[p].z), fabsf(v[p].w))));
        }
        #pragma unroll
        for (int off = 16; off > 0; off >>= 1)
            m = fmaxf(m, __shfl_xor_sync(0xffffffffu, m, off));
        if ((tid & 31) == 0) red[tid >> 5] = m;
        __syncthreads();
        m = red[0];
        #pragma unroll
        for (int i = 1; i < 8; i++) m = fmaxf(m, red[i]);

        const float scale = fmaxf(m / 127.0f, 1e-5f);
        const float inv = 1.0f / scale;
        if (tid == 0) g_so[o] = scale;

        uint2* qr = (uint2*)(g_qw + (size_t)o * K_DIM);
        #pragma unroll
        for (int p = 0; p < 4; p++) {
            __nv_bfloat162 lo = __floats2bfloat162_rn(rintf(v[p].x * inv), rintf(v[p].y * inv));
            __nv_bfloat162 hi = __floats2bfloat162_rn(rintf(v[p].z * inv), rintf(v[p].w * inv));
            uint2 u;
            u.x = *(uint32_t*)&lo;
            u.y = *(uint32_t*)&hi;
            qr[tid + p * 256] = u;
        }
    } else {
        // ======== activation Hadamard+quant path ========
        const int t = blockIdx.x - N_DIM;
        const int l = tid & 31, wv = tid >> 5;
        const float* xr = x + (size_t)t * K_DIM;

        #pragma unroll
        for (int p = 0; p < 16; p++) {
            int e = tid + p * 256;
            s[(e >> 6) * 65 + (e & 63)] = xr[e];
        }
        __syncthreads();

        float r[2][8];
        #pragma unroll
        for (int j = 0; j < 2; j++)
            #pragma unroll
            for (int i = 0; i < 8; i++)
                r[j][i] = s[(l + 32 * j) * 65 + wv * 8 + i];

        #pragma unroll
        for (int i = 0; i < 8; i++) {
            float a = r[0][i], b = r[1][i];
            r[0][i] = a + b;
            r[1][i] = a - b;
        }
        #pragma unroll
        for (int mbit = 1; mbit < 32; mbit <<= 1) {
            const bool hi = (l & mbit) != 0;
            #pragma unroll
            for (int j = 0; j < 2; j++)
                #pragma unroll
                for (int i = 0; i < 8; i++) {
                    float o = __shfl_xor_sync(0xffffffffu, r[j][i], mbit);
                    r[j][i] = hi ? (o - r[j][i]) : (r[j][i] + o);
                }
        }

        float m = 0.f;
        #pragma unroll
        for (int j = 0; j < 2; j++)
            #pragma unroll
            for (int i = 0; i < 8; i++) {
                r[j][i] *= 0.125f;
                m = fmaxf(m, fabsf(r[j][i]));
            }
        #pragma unroll
        for (int off = 16; off > 0; off >>= 1)
            m = fmaxf(m, __shfl_xor_sync(0xffffffffu, m, off));
        if (l == 0) red[wv] = m;
        __syncthreads();
        m = red[0];
        #pragma unroll
        for (int i = 1; i < 8; i++) m = fmaxf(m, red[i]);

        const float scale = fmaxf(m / 127.0f, 1e-5f);
        const float inv = 1.0f / scale;
        if (tid == 0) g_st[t] = scale;

        #pragma unroll
        for (int j = 0; j < 2; j++)
            #pragma unroll
            for (int i = 0; i < 8; i++)
                s[(l + 32 * j) * 65 + wv * 8 + i] = rintf(r[j][i] * inv);
        __syncthreads();

        uint32_t* q32 = (uint32_t*)(g_qx + (size_t)t * K_DIM);
        #pragma unroll
        for (int p = 0; p < 8; p++) {
            int e = 2 * (tid + p * 256);
            int row = e >> 6, col = e & 63;
            __nv_bfloat162 h = __floats2bfloat162_rn(s[row * 65 + col], s[row * 65 + col + 1]);
            q32[tid + p * 256] = *(uint32_t*)&h;
        }
    }
}

// ---------------- GEMM: 128x128x64 tile, 128 threads, warp tile 64x64, 3 CTAs/SM ----------------
#define BM 128
#define BN 128
#define BK 64
#define KITERS (K_DIM / BK)                 // 64
#define PITCH 144                           // bytes per smem row: 64 bf16 + 16B pad
#define TILE_BYTES (BM * PITCH)             // 18432
#define STAGE_BYTES (2 * TILE_BYTES)        // 36864
#define GEMM_SMEM (2 * STAGE_BYTES)         // 73728

__device__ __forceinline__ void mma16816(float d[4], const uint32_t a[4], const uint32_t b[2]) {
    asm volatile(
        "mma.sync.aligned.m16n8k16.row.col.f32.bf16.bf16.f32 "
        "{%0,%1,%2,%3}, {%4,%5,%6,%7}, {%8,%9}, {%0,%1,%2,%3};\n"
        : "+f"(d[0]), "+f"(d[1]), "+f"(d[2]), "+f"(d[3])
        : "r"(a[0]), "r"(a[1]), "r"(a[2]), "r"(a[3]), "r"(b[0]), "r"(b[1]));
}
__device__ __forceinline__ void ldsm_x4(uint32_t r[4], uint32_t addr) {
    asm volatile("ldmatrix.sync.aligned.m8n8.x4.shared.b16 {%0,%1,%2,%3}, [%4];"
                 : "=r"(r[0]), "=r"(r[1]), "=r"(r[2]), "=r"(r[3]) : "r"(addr));
}
__device__ __forceinline__ void cp_async16(uint32_t saddr, const void* gptr) {
    asm volatile("cp.async.cg.shared.global [%0], [%1], 16;" :: "r"(saddr), "l"(gptr));
}
__device__ __forceinline__ uint32_t smem_u32(const void* p) {
    uint32_t a;
    asm("{ .reg .u64 t; cvta.to.shared.u64 t, %1; cvt.u32.u64 %0, t; }" : "=r"(a) : "l"(p));
    return a;
}

__global__ __launch_bounds__(128, 3) void gemm_kernel(float* __restrict__ out,
                                                      const float* __restrict__ bias) {
    extern __shared__ __align__(128) char smem[];
    const uint32_t sbase = smem_u32(smem);

    const int bm = blockIdx.y, bn = blockIdx.x;
    const int tid = threadIdx.x;
    const int wid = tid >> 5, lane = tid & 31;
    const int wm = wid >> 1;       // 0..1 -> 64-row half
    const int wn = wid & 1;        // 0..1 -> 64-col half
    const int grp = lane >> 2;     // 0..7
    const int tig = lane & 3;      // 0..3

    float acc[4][8][4];
    #pragma unroll
    for (int i = 0; i < 4; i++)
        #pragma unroll
        for (int j = 0; j < 8; j++)
            #pragma unroll
            for (int r = 0; r < 4; r++) acc[i][j][r] = 0.f;

    // cp.async loader: row = 128B of k-data (8 x 16B); 16 rows/pass, 8 passes
    const int lrow = tid >> 3;          // 0..15
    const int lcb = (tid & 7) * 16;

    // per-thread hoisted global base pointers (include lane's row and byte slot)
    const char* AgT = (const char*)g_qx + ((size_t)(bm * BM + lrow) * K_DIM) * 2 + lcb;
    const char* BgT = (const char*)g_qw + ((size_t)(bn * BN + lrow) * K_DIM) * 2 + lcb;
    const uint32_t sA = sbase + lrow * PITCH + lcb;
    const uint32_t sB = sA + TILE_BYTES;

    // ldmatrix per-lane bases (within tile)
    const int a_row_in_tile = wm * 64 + (lane & 15);
    const uint32_t a_lane_off = (uint32_t)(a_row_in_tile * PITCH + ((lane & 16) ? 16 : 0));
    const int b_row_in_tile = wn * 64 + (lane & 7) + ((lane & 16) ? 8 : 0);
    const uint32_t b_lane_off = (uint32_t)(b_row_in_tile * PITCH + ((lane & 8) ? 16 : 0));

    // Issue passes [p0,p1) of the 8-row-pass refill for `stage` at k-offset kt.
    auto issue_part = [&](int stage, int kt, int p0, int p1) {
        const uint32_t so = stage * STAGE_BYTES;
        const size_t go = (size_t)kt * 2;
        #pragma unroll
        for (int p = 0; p < 8; p++) {
            if (p < p0 || p >= p1) continue;
            const uint32_t ro = p * (16 * PITCH);
            const size_t gro = (size_t)(p * 16) * (K_DIM * 2) + go;
            cp_async16(sA + so + ro, AgT + gro);
            cp_async16(sB + so + ro, BgT + gro);
        }
    };

    // prologue: fill stage 0 (group g0)
    issue_part(0, 0, 0, 8);
    asm volatile("cp.async.commit_group;" ::: "memory");

    for (int it = 0; it < KITERS; ++it) {
        // Drain the single outstanding group (fills THIS iteration's stage).
        asm volatile("cp.async.wait_group 0;" ::: "memory");
        // One barrier, two roles: visibility for this stage + WAR for the
        // buffer we refill below.
        __syncthreads();

        const uint32_t As = sbase + (it & 1) * STAGE_BYTES;
        const uint32_t Bs = As + TILE_BYTES;
        const int nit = it + 1;
        const int nstage = nit & 1;

        uint32_t a[4][4], b[4][4];

        // ---- ks = 0
        #pragma unroll
        for (int mt = 0; mt < 4; mt++)
            ldsm_x4(a[mt], As + a_lane_off + mt * (16 * PITCH));
        #pragma unroll
        for (int p = 0; p < 4; p++)
            ldsm_x4(b[p], Bs + b_lane_off + p * (16 * PITCH));
        #pragma unroll
        for (int mt = 0; mt < 4; mt++)
            #pragma unroll
            for (int p = 0; p < 4; p++) {
                mma16816(acc[mt][2 * p],     a[mt], &b[p][0]);
                mma16816(acc[mt][2 * p + 1], a[mt], &b[p][2]);
            }

        // refill chunk 1/2 (passes 0-3) under ks0->ks1 shadow
        if (nit < KITERS) issue_part(nstage, nit * BK, 0, 4);

        // ---- ks = 1
        #pragma unroll
        for (int mt = 0; mt < 4; mt++)
            ldsm_x4(a[mt], As + a_lane_off + mt * (16 * PITCH) + 32);
        #pragma unroll
        for (int p = 0; p < 4; p++)
            ldsm_x4(b[p], Bs + b_lane_off + p * (16 * PITCH) + 32);
        #pragma unroll
        for (int mt = 0; mt < 4; mt++)
            #pragma unroll
            for (int p = 0; p < 4; p++) {
                mma16816(acc[mt][2 * p],     a[mt], &b[p][0]);
                mma16816(acc[mt][2 * p + 1], a[mt], &b[p][2]);
            }

        // refill chunk 2/2 (passes 4-7), then commit the single group
        if (nit < KITERS) issue_part(nstage, nit * BK, 4, 8);
        asm volatile("cp.async.commit_group;" ::: "memory");

        // ---- ks = 2..3
        #pragma unroll
        for (int ks = 2; ks < 4; ks++) {
            const int kb = ks * 32;
            #pragma unroll
            for (int mt = 0; mt < 4; mt++)
                ldsm_x4(a[mt], As + a_lane_off + mt * (16 * PITCH) + kb);
            #pragma unroll
            for (int p = 0; p < 4; p++)
                ldsm_x4(b[p], Bs + b_lane_off + p * (16 * PITCH) + kb);
            #pragma unroll
            for (int mt = 0; mt < 4; mt++)
                #pragma unroll
                for (int p = 0; p < 4; p++) {
                    mma16816(acc[mt][2 * p],     a[mt], &b[p][0]);
                    mma16816(acc[mt][2 * p + 1], a[mt], &b[p][2]);
                }
        }
    }
    __syncthreads();

    // epilogue: out = s_t*s_o*acc + bias
    #pragma unroll
    for (int mt = 0; mt < 4; mt++) {
        const int mrow = bm * BM + wm * 64 + mt * 16 + grp;
        const float st0 = g_st[mrow];
        const float st1 = g_st[mrow + 8];
        #pragma unroll
        for (int nt = 0; nt < 8; nt++) {
            const int ncol = bn * BN + wn * 64 + nt * 8 + tig * 2;
            const float so0 = g_so[ncol], so1 = g_so[ncol + 1];
            const float bi0 = bias[ncol], bi1 = bias[ncol + 1];
            float2 v0, v1;
            v0.x = fmaf(st0 * so0, acc[mt][nt][0], bi0);
            v0.y = fmaf(st0 * so1, acc[mt][nt][1], bi1);
            v1.x = fmaf(st1 * so0, acc[mt][nt][2], bi0);
            v1.y = fmaf(st1 * so1, acc[mt][nt][3], bi1);
            *(float2*)&out[(size_t)mrow * N_DIM + ncol] = v0;
            *(float2*)&out[(size_t)(mrow + 8) * N_DIM + ncol] = v1;
        }
    }
}

// ---------------- launcher ----------------
extern "C" void kernel_launch(void* const* d_in, const int* in_sizes, int n_in,
                              void* d_out, int out_size) {
    const float* x = (const float*)d_in[0];
    const float* w = (const float*)d_in[1];
    const float* bias = (const float*)d_in[2];
    float* out = (float*)d_out;
    (void)in_sizes; (void)n_in; (void)out_size;

    prep_kernel<<<N_DIM + M_DIM, 256>>>(w, x);

    cudaFuncSetAttribute(gemm_kernel, cudaFuncAttributeMaxDynamicSharedMemorySize, GEMM_SMEM);
    dim3 grid(N_DIM / BN, M_DIM / BM);
    gemm_kernel<<<grid, 128, GEMM_SMEM>>>(out, bias);
}

// round 16
// speedup vs baseline: 1.0069x; 1.0069x over previous
#include <cuda_runtime.h>
#include <cuda_bf16.h>
#include <cstdint>

// Shapes fixed by the problem.
#define M_DIM 4096
#define N_DIM 4096
#define K_DIM 4096

// ---------------- scratch (static __device__; no runtime alloc) ----------------
__device__ __align__(256) __nv_bfloat16 g_qx[(size_t)M_DIM * K_DIM];  // quantized activations (ints in bf16)
__device__ __align__(256) __nv_bfloat16 g_qw[(size_t)N_DIM * K_DIM];  // quantized weights (ints in bf16)
__device__ float g_st[M_DIM];
__device__ float g_so[N_DIM];

// ---------------- fused prep kernel ----------------
__global__ __launch_bounds__(256) void prep_kernel(const float* __restrict__ w,
                                                   const float* __restrict__ x) {
    __shared__ float s[64 * 65];
    __shared__ float red[8];
    const int tid = threadIdx.x;

    if (blockIdx.x < N_DIM) {
        // ======== weight quant path ========
        const int o = blockIdx.x;
        const float4* wr = (const float4*)(w + (size_t)o * K_DIM);

        float4 v[4];
        float m = 0.f;
        #pragma unroll
        for (int p = 0; p < 4; p++) {
            v[p] = wr[tid + p * 256];
            m = fmaxf(m, fmaxf(fmaxf(fabsf(v[p].x), fabsf(v[p].y)),
                               fmaxf(fabsf(v[p].z), fabsf(v[p].w))));
        }
        #pragma unroll
        for (int off = 16; off > 0; off >>= 1)
            m = fmaxf(m, __shfl_xor_sync(0xffffffffu, m, off));
        if ((tid & 31) == 0) red[tid >> 5] = m;
        __syncthreads();
        m = red[0];
        #pragma unroll
        for (int i = 1; i < 8; i++) m = fmaxf(m, red[i]);

        const float scale = fmaxf(m / 127.0f, 1e-5f);
        const float inv = 1.0f / scale;
        if (tid == 0) g_so[o] = scale;

        uint2* qr = (uint2*)(g_qw + (size_t)o * K_DIM);
        #pragma unroll
        for (int p = 0; p < 4; p++) {
            __nv_bfloat162 lo = __floats2bfloat162_rn(rintf(v[p].x * inv), rintf(v[p].y * inv));
            __nv_bfloat162 hi = __floats2bfloat162_rn(rintf(v[p].z * inv), rintf(v[p].w * inv));
            uint2 u;
            u.x = *(uint32_t*)&lo;
            u.y = *(uint32_t*)&hi;
            qr[tid + p * 256] = u;
        }
    } else {
        // ======== activation Hadamard+quant path ========
        const int t = blockIdx.x - N_DIM;
        const int l = tid & 31, wv = tid >> 5;
        const float4* xr4 = (const float4*)(x + (size_t)t * K_DIM);

        // coalesced float4 loads -> padded smem transpose (pitch 65)
        #pragma unroll
        for (int p = 0; p < 4; p++) {
            float4 v = xr4[tid + p * 256];
            int e = 4 * (tid + p * 256);
            int row = e >> 6, col = e & 63;
            float* sr = &s[row * 65 + col];
            sr[0] = v.x; sr[1] = v.y; sr[2] = v.z; sr[3] = v.w;
        }
        __syncthreads();

        // thread (wv,l) holds d = wv*8 + i (i<8), g = l + 32*j (j<2)
        float r[2][8];
        #pragma unroll
        for (int j = 0; j < 2; j++)
            #pragma unroll
            for (int i = 0; i < 8; i++)
                r[j][i] = s[(l + 32 * j) * 65 + wv * 8 + i];

        #pragma unroll
        for (int i = 0; i < 8; i++) {
            float a = r[0][i], b = r[1][i];
            r[0][i] = a + b;
            r[1][i] = a - b;
        }
        #pragma unroll
        for (int mbit = 1; mbit < 32; mbit <<= 1) {
            const bool hi = (l & mbit) != 0;
            #pragma unroll
            for (int j = 0; j < 2; j++)
                #pragma unroll
                for (int i = 0; i < 8; i++) {
                    float o = __shfl_xor_sync(0xffffffffu, r[j][i], mbit);
                    r[j][i] = hi ? (o - r[j][i]) : (r[j][i] + o);
                }
        }

        float m = 0.f;
        #pragma unroll
        for (int j = 0; j < 2; j++)
            #pragma unroll
            for (int i = 0; i < 8; i++) {
                r[j][i] *= 0.125f;
                m = fmaxf(m, fabsf(r[j][i]));
            }
        #pragma unroll
        for (int off = 16; off > 0; off >>= 1)
            m = fmaxf(m, __shfl_xor_sync(0xffffffffu, m, off));
        if (l == 0) red[wv] = m;
        __syncthreads();
        m = red[0];
        #pragma unroll
        for (int i = 1; i < 8; i++) m = fmaxf(m, red[i]);

        const float scale = fmaxf(m / 127.0f, 1e-5f);
        const float inv = 1.0f / scale;
        if (tid == 0) g_st[t] = scale;

        // direct register -> global store: thread owns rows g=l+32j,
        // 8 contiguous bf16 at column wv*8 (16B aligned). No smem round-trip.
        #pragma unroll
        for (int j = 0; j < 2; j++) {
            __nv_bfloat162 h0 = __floats2bfloat162_rn(rintf(r[j][0] * inv), rintf(r[j][1] * inv));
            __nv_bfloat162 h1 = __floats2bfloat162_rn(rintf(r[j][2] * inv), rintf(r[j][3] * inv));
            __nv_bfloat162 h2 = __floats2bfloat162_rn(rintf(r[j][4] * inv), rintf(r[j][5] * inv));
            __nv_bfloat162 h3 = __floats2bfloat162_rn(rintf(r[j][6] * inv), rintf(r[j][7] * inv));
            uint4 u;
            u.x = *(uint32_t*)&h0;
            u.y = *(uint32_t*)&h1;
            u.z = *(uint32_t*)&h2;
            u.w = *(uint32_t*)&h3;
            const int g = l + 32 * j;
            *(uint4*)(g_qx + (size_t)t * K_DIM + g * 64 + wv * 8) = u;
        }
    }
}

// ---------------- GEMM: 128x128x64 tile, 128 threads, warp tile 64x64, 3 CTAs/SM ----------------
// (byte-identical to the round-14 champion)
#define BM 128
#define BN 128
#define BK 64
#define KITERS (K_DIM / BK)                 // 64
#define PITCH 144                           // bytes per smem row: 64 bf16 + 16B pad
#define TILE_BYTES (BM * PITCH)             // 18432
#define STAGE_BYTES (2 * TILE_BYTES)        // 36864
#define GEMM_SMEM (2 * STAGE_BYTES)         // 73728

__device__ __forceinline__ void mma16816(float d[4], const uint32_t a[4], const uint32_t b[2]) {
    asm volatile(
        "mma.sync.aligned.m16n8k16.row.col.f32.bf16.bf16.f32 "
        "{%0,%1,%2,%3}, {%4,%5,%6,%7}, {%8,%9}, {%0,%1,%2,%3};\n"
        : "+f"(d[0]), "+f"(d[1]), "+f"(d[2]), "+f"(d[3])
        : "r"(a[0]), "r"(a[1]), "r"(a[2]), "r"(a[3]), "r"(b[0]), "r"(b[1]));
}
__device__ __forceinline__ void ldsm_x4(uint32_t r[4], uint32_t addr) {
    asm volatile("ldmatrix.sync.aligned.m8n8.x4.shared.b16 {%0,%1,%2,%3}, [%4];"
                 : "=r"(r[0]), "=r"(r[1]), "=r"(r[2]), "=r"(r[3]) : "r"(addr));
}
__device__ __forceinline__ void cp_async16(uint32_t saddr, const void* gptr) {
    asm volatile("cp.async.cg.shared.global [%0], [%1], 16;" :: "r"(saddr), "l"(gptr));
}
__device__ __forceinline__ uint32_t smem_u32(const void* p) {
    uint32_t a;
    asm("{ .reg .u64 t; cvta.to.shared.u64 t, %1; cvt.u32.u64 %0, t; }" : "=r"(a) : "l"(p));
    return a;
}

__global__ __launch_bounds__(128, 3) void gemm_kernel(float* __restrict__ out,
                                                      const float* __restrict__ bias) {
    extern __shared__ __align__(128) char smem[];
    const uint32_t sbase = smem_u32(smem);

    const int bm = blockIdx.y, bn = blockIdx.x;
    const int tid = threadIdx.x;
    const int wid = tid >> 5, lane = tid & 31;
    const int wm = wid >> 1;       // 0..1 -> 64-row half
    const int wn = wid & 1;        // 0..1 -> 64-col half
    const int grp = lane >> 2;     // 0..7
    const int tig = lane & 3;      // 0..3

    float acc[4][8][4];
    #pragma unroll
    for (int i = 0; i < 4; i++)
        #pragma unroll
        for (int j = 0; j < 8; j++)
            #pragma unroll
            for (int r = 0; r < 4; r++) acc[i][j][r] = 0.f;

    const char* Ag = (const char*)g_qx + (size_t)(bm * BM) * K_DIM * 2;
    const char* Bg = (const char*)g_qw + (size_t)(bn * BN) * K_DIM * 2;

    // cp.async loader: row = 128B of k-data (8 x 16B); 16 rows/pass, 8 passes
    const int lrow = tid >> 3;          // 0..15
    const int lcb = (tid & 7) * 16;

    // ldmatrix per-lane bases (within tile)
    const int a_row_in_tile = wm * 64 + (lane & 15);
    const uint32_t a_lane_off = (uint32_t)(a_row_in_tile * PITCH + ((lane & 16) ? 16 : 0));
    const int b_row_in_tile = wn * 64 + (lane & 7) + ((lane & 16) ? 8 : 0);
    const uint32_t b_lane_off = (uint32_t)(b_row_in_tile * PITCH + ((lane & 8) ? 16 : 0));

    auto issue_stage = [&](int stage, int kt) {
        const uint32_t sa = sbase + stage * STAGE_BYTES;
        const uint32_t sbb = sa + TILE_BYTES;
        const size_t gofs = (size_t)kt * 2 + lcb;
        #pragma unroll
        for (int p = 0; p < 8; p++) {
            const int row = lrow + p * 16;
            cp_async16(sa  + row * PITCH + lcb, Ag + (size_t)row * (K_DIM * 2) + gofs);
            cp_async16(sbb + row * PITCH + lcb, Bg + (size_t)row * (K_DIM * 2) + gofs);
        }
    };

    // prologue: fill stage 0 (group g0)
    issue_stage(0, 0);
    asm volatile("cp.async.commit_group;" ::: "memory");

    for (int it = 0; it < KITERS; ++it) {
        // Drain the single outstanding group (fills THIS iteration's stage).
        asm volatile("cp.async.wait_group 0;" ::: "memory");
        // One barrier, two roles: visibility for this stage + WAR for the
        // buffer we refill below.
        __syncthreads();

        const uint32_t As = sbase + (it & 1) * STAGE_BYTES;
        const uint32_t Bs = As + TILE_BYTES;

        uint32_t a[4][4], b[4][4];

        // ---- ks = 0: fragments + HMMA first, so the cp.async burst below
        // issues under the HMMA shadow instead of blocking LDSM in MIO.
        #pragma unroll
        for (int mt = 0; mt < 4; mt++)
            ldsm_x4(a[mt], As + a_lane_off + mt * (16 * PITCH));
        #pragma unroll
        for (int p = 0; p < 4; p++)
            ldsm_x4(b[p], Bs + b_lane_off + p * (16 * PITCH));
        #pragma unroll
        for (int mt = 0; mt < 4; mt++)
            #pragma unroll
            for (int p = 0; p < 4; p++) {
                mma16816(acc[mt][2 * p],     a[mt], &b[p][0]);
                mma16816(acc[mt][2 * p + 1], a[mt], &b[p][2]);
            }

        // ---- refill next stage now (overlaps ks1..3 compute)
        const int nit = it + 1;
        if (nit < KITERS) issue_stage(nit & 1, nit * BK);
        asm volatile("cp.async.commit_group;" ::: "memory");

        // ---- ks = 1..3
        #pragma unroll
        for (int ks = 1; ks < 4; ks++) {
            const int kb = ks * 32;
            #pragma unroll
            for (int mt = 0; mt < 4; mt++)
                ldsm_x4(a[mt], As + a_lane_off + mt * (16 * PITCH) + kb);
            #pragma unroll
            for (int p = 0; p < 4; p++)
                ldsm_x4(b[p], Bs + b_lane_off + p * (16 * PITCH) + kb);
            #pragma unroll
            for (int mt = 0; mt < 4; mt++)
                #pragma unroll
                for (int p = 0; p < 4; p++) {
                    mma16816(acc[mt][2 * p],     a[mt], &b[p][0]);
                    mma16816(acc[mt][2 * p + 1], a[mt], &b[p][2]);
                }
        }
    }
    __syncthreads();

    // epilogue: out = s_t*s_o*acc + bias
    #pragma unroll
    for (int mt = 0; mt < 4; mt++) {
        const int mrow = bm * BM + wm * 64 + mt * 16 + grp;
        const float st0 = g_st[mrow];
        const float st1 = g_st[mrow + 8];
        #pragma unroll
        for (int nt = 0; nt < 8; nt++) {
            const int ncol = bn * BN + wn * 64 + nt * 8 + tig * 2;
            const float so0 = g_so[ncol], so1 = g_so[ncol + 1];
            const float bi0 = bias[ncol], bi1 = bias[ncol + 1];
            float2 v0, v1;
            v0.x = fmaf(st0 * so0, acc[mt][nt][0], bi0);
            v0.y = fmaf(st0 * so1, acc[mt][nt][1], bi1);
            v1.x = fmaf(st1 * so0, acc[mt][nt][2], bi0);
            v1.y = fmaf(st1 * so1, acc[mt][nt][3], bi1);
            *(float2*)&out[(size_t)mrow * N_DIM + ncol] = v0;
            *(float2*)&out[(size_t)(mrow + 8) * N_DIM + ncol] = v1;
        }
    }
}

// ---------------- launcher ----------------
extern "C" void kernel_launch(void* const* d_in, const int* in_sizes, int n_in,
                              void* d_out, int out_size) {
    const float* x = (const float*)d_in[0];
    const float* w = (const float*)d_in[1];
    const float* bias = (const float*)d_in[2];
    float* out = (float*)d_out;
    (void)in_sizes; (void)n_in; (void)out_size;

    prep_kernel<<<N_DIM + M_DIM, 256>>>(w, x);

    cudaFuncSetAttribute(gemm_kernel, cudaFuncAttributeMaxDynamicSharedMemorySize, GEMM_SMEM);
    dim3 grid(N_DIM / BN, M_DIM / BM);
    gemm_kernel<<<grid, 128, GEMM_SMEM>>>(out, bias);
}

// round 17
// speedup vs baseline: 1.0130x; 1.0061x over previous
#include <cuda_runtime.h>
#include <cuda_bf16.h>
#include <cstdint>

// Shapes fixed by the problem.
#define M_DIM 4096
#define N_DIM 4096
#define K_DIM 4096

// ---------------- scratch (static __device__; no runtime alloc) ----------------
__device__ __align__(256) __nv_bfloat16 g_qx[(size_t)M_DIM * K_DIM];  // quantized activations (ints in bf16)
__device__ __align__(256) __nv_bfloat16 g_qw[(size_t)N_DIM * K_DIM];  // quantized weights (ints in bf16)
__device__ float g_st[M_DIM];
__device__ float g_so[N_DIM];

// ---------------- fused prep kernel ----------------
__global__ __launch_bounds__(256) void prep_kernel(const float* __restrict__ w,
                                                   const float* __restrict__ x) {
    __shared__ float s[64 * 65];
    __shared__ float red[8];
    const int tid = threadIdx.x;

    if (blockIdx.x < N_DIM) {
        // ======== weight quant path ========
        const int o = blockIdx.x;
        const float4* wr = (const float4*)(w + (size_t)o * K_DIM);

        float4 v[4];
        float m = 0.f;
        #pragma unroll
        for (int p = 0; p < 4; p++) {
            v[p] = wr[tid + p * 256];
            m = fmaxf(m, fmaxf(fmaxf(fabsf(v[p].x), fabsf(v[p].y)),
                               fmaxf(fabsf(v[p].z), fabsf(v[p].w))));
        }
        #pragma unroll
        for (int off = 16; off > 0; off >>= 1)
            m = fmaxf(m, __shfl_xor_sync(0xffffffffu, m, off));
        if ((tid & 31) == 0) red[tid >> 5] = m;
        __syncthreads();
        m = red[0];
        #pragma unroll
        for (int i = 1; i < 8; i++) m = fmaxf(m, red[i]);

        const float scale = fmaxf(m / 127.0f, 1e-5f);
        const float inv = 1.0f / scale;
        if (tid == 0) g_so[o] = scale;

        uint2* qr = (uint2*)(g_qw + (size_t)o * K_DIM);
        #pragma unroll
        for (int p = 0; p < 4; p++) {
            __nv_bfloat162 lo = __floats2bfloat162_rn(rintf(v[p].x * inv), rintf(v[p].y * inv));
            __nv_bfloat162 hi = __floats2bfloat162_rn(rintf(v[p].z * inv), rintf(v[p].w * inv));
            uint2 u;
            u.x = *(uint32_t*)&lo;
            u.y = *(uint32_t*)&hi;
            qr[tid + p * 256] = u;
        }
    } else {
        // ======== activation Hadamard+quant path ========
        const int t = blockIdx.x - N_DIM;
        const int l = tid & 31, wv = tid >> 5;
        const float4* xr4 = (const float4*)(x + (size_t)t * K_DIM);

        // coalesced float4 loads -> padded smem transpose (pitch 65)
        #pragma unroll
        for (int p = 0; p < 4; p++) {
            float4 v = xr4[tid + p * 256];
            int e = 4 * (tid + p * 256);
            int row = e >> 6, col = e & 63;
            float* sr = &s[row * 65 + col];
            sr[0] = v.x; sr[1] = v.y; sr[2] = v.z; sr[3] = v.w;
        }
        __syncthreads();

        // thread (wv,l) holds d = wv*8 + i (i<8), g = l + 32*j (j<2)
        float r[2][8];
        #pragma unroll
        for (int j = 0; j < 2; j++)
            #pragma unroll
            for (int i = 0; i < 8; i++)
                r[j][i] = s[(l + 32 * j) * 65 + wv * 8 + i];

        #pragma unroll
        for (int i = 0; i < 8; i++) {
            float a = r[0][i], b = r[1][i];
            r[0][i] = a + b;
            r[1][i] = a - b;
        }
        #pragma unroll
        for (int mbit = 1; mbit < 32; mbit <<= 1) {
            const bool hi = (l & mbit) != 0;
            #pragma unroll
            for (int j = 0; j < 2; j++)
                #pragma unroll
                for (int i = 0; i < 8; i++) {
                    float o = __shfl_xor_sync(0xffffffffu, r[j][i], mbit);
                    r[j][i] = hi ? (o - r[j][i]) : (r[j][i] + o);
                }
        }

        float m = 0.f;
        #pragma unroll
        for (int j = 0; j < 2; j++)
            #pragma unroll
            for (int i = 0; i < 8; i++) {
                r[j][i] *= 0.125f;
                m = fmaxf(m, fabsf(r[j][i]));
            }
        #pragma unroll
        for (int off = 16; off > 0; off >>= 1)
            m = fmaxf(m, __shfl_xor_sync(0xffffffffu, m, off));
        if (l == 0) red[wv] = m;
        __syncthreads();
        m = red[0];
        #pragma unroll
        for (int i = 1; i < 8; i++) m = fmaxf(m, red[i]);

        const float scale = fmaxf(m / 127.0f, 1e-5f);
        const float inv = 1.0f / scale;
        if (tid == 0) g_st[t] = scale;

        // quantize back to smem, then fully-coalesced bf16x2 global stores
        #pragma unroll
        for (int j = 0; j < 2; j++)
            #pragma unroll
            for (int i = 0; i < 8; i++)
                s[(l + 32 * j) * 65 + wv * 8 + i] = rintf(r[j][i] * inv);
        __syncthreads();

        uint32_t* q32 = (uint32_t*)(g_qx + (size_t)t * K_DIM);
        #pragma unroll
        for (int p = 0; p < 8; p++) {
            int e = 2 * (tid + p * 256);
            int row = e >> 6, col = e & 63;
            __nv_bfloat162 h = __floats2bfloat162_rn(s[row * 65 + col], s[row * 65 + col + 1]);
            q32[tid + p * 256] = *(uint32_t*)&h;
        }
    }
}

// ---------------- GEMM: 128x128x64 tile, 128 threads, warp tile 64x64, 3 CTAs/SM ----------------
// (byte-identical to the round-16/14 champion mainloop)
#define BM 128
#define BN 128
#define BK 64
#define KITERS (K_DIM / BK)                 // 64
#define PITCH 144                           // bytes per smem row: 64 bf16 + 16B pad
#define TILE_BYTES (BM * PITCH)             // 18432
#define STAGE_BYTES (2 * TILE_BYTES)        // 36864
#define GEMM_SMEM (2 * STAGE_BYTES)         // 73728

__device__ __forceinline__ void mma16816(float d[4], const uint32_t a[4], const uint32_t b[2]) {
    asm volatile(
        "mma.sync.aligned.m16n8k16.row.col.f32.bf16.bf16.f32 "
        "{%0,%1,%2,%3}, {%4,%5,%6,%7}, {%8,%9}, {%0,%1,%2,%3};\n"
        : "+f"(d[0]), "+f"(d[1]), "+f"(d[2]), "+f"(d[3])
        : "r"(a[0]), "r"(a[1]), "r"(a[2]), "r"(a[3]), "r"(b[0]), "r"(b[1]));
}
__device__ __forceinline__ void ldsm_x4(uint32_t r[4], uint32_t addr) {
    asm volatile("ldmatrix.sync.aligned.m8n8.x4.shared.b16 {%0,%1,%2,%3}, [%4];"
                 : "=r"(r[0]), "=r"(r[1]), "=r"(r[2]), "=r"(r[3]) : "r"(addr));
}
__device__ __forceinline__ void cp_async16(uint32_t saddr, const void* gptr) {
    asm volatile("cp.async.cg.shared.global [%0], [%1], 16;" :: "r"(saddr), "l"(gptr));
}
__device__ __forceinline__ uint32_t smem_u32(const void* p) {
    uint32_t a;
    asm("{ .reg .u64 t; cvta.to.shared.u64 t, %1; cvt.u32.u64 %0, t; }" : "=r"(a) : "l"(p));
    return a;
}

__global__ __launch_bounds__(128, 3) void gemm_kernel(float* __restrict__ out,
                                                      const float* __restrict__ bias) {
    extern __shared__ __align__(128) char smem[];
    const uint32_t sbase = smem_u32(smem);

    const int bm = blockIdx.y, bn = blockIdx.x;
    const int tid = threadIdx.x;
    const int wid = tid >> 5, lane = tid & 31;
    const int wm = wid >> 1;       // 0..1 -> 64-row half
    const int wn = wid & 1;        // 0..1 -> 64-col half
    const int grp = lane >> 2;     // 0..7
    const int tig = lane & 3;      // 0..3

    float acc[4][8][4];
    #pragma unroll
    for (int i = 0; i < 4; i++)
        #pragma unroll
        for (int j = 0; j < 8; j++)
            #pragma unroll
            for (int r = 0; r < 4; r++) acc[i][j][r] = 0.f;

    const char* Ag = (const char*)g_qx + (size_t)(bm * BM) * K_DIM * 2;
    const char* Bg = (const char*)g_qw + (size_t)(bn * BN) * K_DIM * 2;

    // cp.async loader: row = 128B of k-data (8 x 16B); 16 rows/pass, 8 passes
    const int lrow = tid >> 3;          // 0..15
    const int lcb = (tid & 7) * 16;

    // ldmatrix per-lane bases (within tile)
    const int a_row_in_tile = wm * 64 + (lane & 15);
    const uint32_t a_lane_off = (uint32_t)(a_row_in_tile * PITCH + ((lane & 16) ? 16 : 0));
    const int b_row_in_tile = wn * 64 + (lane & 7) + ((lane & 16) ? 8 : 0);
    const uint32_t b_lane_off = (uint32_t)(b_row_in_tile * PITCH + ((lane & 8) ? 16 : 0));

    auto issue_stage = [&](int stage, int kt) {
        const uint32_t sa = sbase + stage * STAGE_BYTES;
        const uint32_t sbb = sa + TILE_BYTES;
        const size_t gofs = (size_t)kt * 2 + lcb;
        #pragma unroll
        for (int p = 0; p < 8; p++) {
            const int row = lrow + p * 16;
            cp_async16(sa  + row * PITCH + lcb, Ag + (size_t)row * (K_DIM * 2) + gofs);
            cp_async16(sbb + row * PITCH + lcb, Bg + (size_t)row * (K_DIM * 2) + gofs);
        }
    };

    // prologue: fill stage 0 (group g0)
    issue_stage(0, 0);
    asm volatile("cp.async.commit_group;" ::: "memory");

    for (int it = 0; it < KITERS; ++it) {
        // Drain the single outstanding group (fills THIS iteration's stage).
        asm volatile("cp.async.wait_group 0;" ::: "memory");
        // One barrier, two roles: visibility for this stage + WAR for the
        // buffer we refill below.
        __syncthreads();

        const uint32_t As = sbase + (it & 1) * STAGE_BYTES;
        const uint32_t Bs = As + TILE_BYTES;

        uint32_t a[4][4], b[4][4];

        // ---- ks = 0: fragments + HMMA first, so the cp.async burst below
        // issues under the HMMA shadow instead of blocking LDSM in MIO.
        #pragma unroll
        for (int mt = 0; mt < 4; mt++)
            ldsm_x4(a[mt], As + a_lane_off + mt * (16 * PITCH));
        #pragma unroll
        for (int p = 0; p < 4; p++)
            ldsm_x4(b[p], Bs + b_lane_off + p * (16 * PITCH));
        #pragma unroll
        for (int mt = 0; mt < 4; mt++)
            #pragma unroll
            for (int p = 0; p < 4; p++) {
                mma16816(acc[mt][2 * p],     a[mt], &b[p][0]);
                mma16816(acc[mt][2 * p + 1], a[mt], &b[p][2]);
            }

        // ---- refill next stage now (overlaps ks1..3 compute)
        const int nit = it + 1;
        if (nit < KITERS) issue_stage(nit & 1, nit * BK);
        asm volatile("cp.async.commit_group;" ::: "memory");

        // ---- ks = 1..3
        #pragma unroll
        for (int ks = 1; ks < 4; ks++) {
            const int kb = ks * 32;
            #pragma unroll
            for (int mt = 0; mt < 4; mt++)
                ldsm_x4(a[mt], As + a_lane_off + mt * (16 * PITCH) + kb);
            #pragma unroll
            for (int p = 0; p < 4; p++)
                ldsm_x4(b[p], Bs + b_lane_off + p * (16 * PITCH) + kb);
            #pragma unroll
            for (int mt = 0; mt < 4; mt++)
                #pragma unroll
                for (int p = 0; p < 4; p++) {
                    mma16816(acc[mt][2 * p],     a[mt], &b[p][0]);
                    mma16816(acc[mt][2 * p + 1], a[mt], &b[p][2]);
                }
        }
    }
    __syncthreads();

    // epilogue: out = s_t*s_o*acc + bias
    #pragma unroll
    for (int mt = 0; mt < 4; mt++) {
        const int mrow = bm * BM + wm * 64 + mt * 16 + grp;
        const float st0 = g_st[mrow];
        const float st1 = g_st[mrow + 8];
        #pragma unroll
        for (int nt = 0; nt < 8; nt++) {
            const int ncol = bn * BN + wn * 64 + nt * 8 + tig * 2;
            const float so0 = g_so[ncol], so1 = g_so[ncol + 1];
            const float bi0 = bias[ncol], bi1 = bias[ncol + 1];
            float2 v0, v1;
            v0.x = fmaf(st0 * so0, acc[mt][nt][0], bi0);
            v0.y = fmaf(st0 * so1, acc[mt][nt][1], bi1);
            v1.x = fmaf(st1 * so0, acc[mt][nt][2], bi0);
            v1.y = fmaf(st1 * so1, acc[mt][nt][3], bi1);
            *(float2*)&out[(size_t)mrow * N_DIM + ncol] = v0;
            *(float2*)&out[(size_t)(mrow + 8) * N_DIM + ncol] = v1;
        }
    }
}

// ---------------- launcher ----------------
extern "C" void kernel_launch(void* const* d_in, const int* in_sizes, int n_in,
                              void* d_out, int out_size) {
    const float* x = (const float*)d_in[0];
    const float* w = (const float*)d_in[1];
    const float* bias = (const float*)d_in[2];
    float* out = (float*)d_out;
    (void)in_sizes; (void)n_in; (void)out_size;

    prep_kernel<<<N_DIM + M_DIM, 256>>>(w, x);

    cudaFuncSetAttribute(gemm_kernel, cudaFuncAttributeMaxDynamicSharedMemorySize, GEMM_SMEM);
    dim3 grid(N_DIM / BN, M_DIM / BM);
    gemm_kernel<<<grid, 128, GEMM_SMEM>>>(out, bias);
}